// round 1
// baseline (speedup 1.0000x reference)
#include <cuda_runtime.h>

// ---------------- problem constants ----------------
#define Bb    32
#define Tt    128
#define Pp    512
#define NDd   2
#define MAXL  7
#define Dd    300
#define DPAD  304          // K padded to multiple of 8
#define Kk    (Pp*NDd*MAXL)  // 7168
#define Mm    (Bb*Tt)        // 4096
#define NCc   2
#define NEGV  (-1e30f)

// ---------------- scratch (static device globals; no allocs) ----------------
__device__ float g_ts[(size_t)Mm * Kk];      // 117 MB  transition scores [m=b*T+t][k]
__device__ float g_A [(size_t)Mm * DPAD];    // gathered+padded embeddings
__device__ float g_Bm[(size_t)Kk * DPAD];    // padded diags
__device__ float g_scores[Bb * Pp];          // per (b,p) max-sum score

// ---------------- 1. gather embeddings, zero-pad K ----------------
__global__ void gather_kernel(const int* __restrict__ tokens,
                              const float* __restrict__ emb_table)
{
    int m = blockIdx.x;                         // 0..4095
    int tok = tokens[m];
    const float* src = emb_table + (size_t)tok * Dd;
    float* dst = g_A + (size_t)m * DPAD;
    for (int k = threadIdx.x; k < DPAD; k += blockDim.x)
        dst[k] = (k < Dd) ? src[k] : 0.0f;
}

// ---------------- 2. pad diags rows to DPAD ----------------
__global__ void padB_kernel(const float* __restrict__ diags)
{
    int n = blockIdx.x;                         // 0..7167
    const float* src = diags + (size_t)n * Dd;
    float* dst = g_Bm + (size_t)n * DPAD;
    for (int k = threadIdx.x; k < DPAD; k += blockDim.x)
        dst[k] = (k < Dd) ? src[k] : 0.0f;
}

// ---------------- 3. SGEMM (NT): ts[m,n] = sum_k A[m,k]*B[n,k] + bias[n] ----------------
// 128x128 tile, BK=8, 256 threads, 8x8 per-thread microtile.
__global__ __launch_bounds__(256) void gemm_kernel(const float* __restrict__ bias)
{
    __shared__ float As[8][128];
    __shared__ float Bs[8][128];

    const int tid = threadIdx.x;
    const int tx  = tid & 15;        // 0..15 (N dir)
    const int ty  = tid >> 4;        // 0..15 (M dir)
    const int blockM = blockIdx.y * 128;
    const int blockN = blockIdx.x * 128;

    const int lRow = tid >> 1;       // 0..127
    const int lK4  = (tid & 1) * 4;  // 0 or 4

    const float* Aptr = g_A  + (size_t)(blockM + lRow) * DPAD + lK4;
    const float* Bptr = g_Bm + (size_t)(blockN + lRow) * DPAD + lK4;

    float acc[8][8];
    #pragma unroll
    for (int i = 0; i < 8; i++)
        #pragma unroll
        for (int j = 0; j < 8; j++) acc[i][j] = 0.0f;

    for (int k0 = 0; k0 < DPAD; k0 += 8) {
        float4 av = *(const float4*)(Aptr + k0);
        float4 bv = *(const float4*)(Bptr + k0);
        As[lK4+0][lRow] = av.x; As[lK4+1][lRow] = av.y;
        As[lK4+2][lRow] = av.z; As[lK4+3][lRow] = av.w;
        Bs[lK4+0][lRow] = bv.x; Bs[lK4+1][lRow] = bv.y;
        Bs[lK4+2][lRow] = bv.z; Bs[lK4+3][lRow] = bv.w;
        __syncthreads();

        #pragma unroll
        for (int kk = 0; kk < 8; kk++) {
            float a[8], b[8];
            #pragma unroll
            for (int i = 0; i < 8; i++) a[i] = As[kk][ty*8 + i];
            #pragma unroll
            for (int j = 0; j < 8; j++) b[j] = Bs[kk][tx*8 + j];
            #pragma unroll
            for (int i = 0; i < 8; i++)
                #pragma unroll
                for (int j = 0; j < 8; j++)
                    acc[i][j] += a[i] * b[j];
        }
        __syncthreads();
    }

    // epilogue: add bias, vectorized store
    const int ncol = blockN + tx*8;
    float bsv[8];
    #pragma unroll
    for (int j = 0; j < 8; j++) bsv[j] = bias[ncol + j];

    #pragma unroll
    for (int i = 0; i < 8; i++) {
        int m = blockM + ty*8 + i;
        float* crow = g_ts + (size_t)m * Kk + ncol;
        float4 v0, v1;
        v0.x = acc[i][0] + bsv[0]; v0.y = acc[i][1] + bsv[1];
        v0.z = acc[i][2] + bsv[2]; v0.w = acc[i][3] + bsv[3];
        v1.x = acc[i][4] + bsv[4]; v1.y = acc[i][5] + bsv[5];
        v1.z = acc[i][6] + bsv[6]; v1.w = acc[i][7] + bsv[7];
        *(float4*)(crow)     = v0;
        *(float4*)(crow + 4) = v1;
    }
}

// ---------------- 4. max-sum semiring scan over T (one thread per (b,p)) ----------------
__global__ void scan_kernel(const int* __restrict__ doc_lens,
                            const float* __restrict__ epsilons)
{
    int idx = blockIdx.x * blockDim.x + threadIdx.x;
    if (idx >= Bb * Pp) return;
    int b = idx / Pp;
    int p = idx % Pp;

    float eps[6];
    #pragma unroll
    for (int i = 0; i < 6; i++) eps[i] = epsilons[p*6 + i];
    const bool end5 = (p < 256);     // END_STATES: 5 for first 256 patterns, else 6
    const int dl = doc_lens[b];

    float hid[7];
    hid[0] = 0.0f;
    #pragma unroll
    for (int m = 1; m < 7; m++) hid[m] = NEGV;
    float sc = NEGV;

    const float* base = g_ts + (size_t)b * Tt * Kk + (size_t)p * (NDd*MAXL);

    for (int t = 0; t < Tt; t++) {
        const float* tm = base + (size_t)t * Kk;
        float tm0[7], tm1[7];
        #pragma unroll
        for (int m = 0; m < 7; m++) tm0[m] = tm[m];        // d=0 self-loop
        #pragma unroll
        for (int m = 0; m < 7; m++) tm1[m] = tm[7 + m];    // d=1 main diag

        // epsilon transitions
        float ae[7];
        ae[0] = hid[0];
        #pragma unroll
        for (int m = 1; m < 7; m++) ae[m] = fmaxf(hid[m], hid[m-1] + eps[m-1]);

        // main-diag (with restart padding 0.0 at state 0) vs self-loop
        float nh[7];
        nh[0] = fmaxf(0.0f, ae[0] + tm0[0]);
        #pragma unroll
        for (int m = 1; m < 7; m++)
            nh[m] = fmaxf(ae[m-1] + tm1[m-1], ae[m] + tm0[m]);
        #pragma unroll
        for (int m = 0; m < 7; m++) hid[m] = nh[m];

        float endv = end5 ? hid[5] : hid[6];
        if (t < dl) sc = fmaxf(sc, endv);
    }
    g_scores[idx] = sc;
}

// ---------------- 5. batchnorm + binarize + final linear ----------------
__global__ __launch_bounds__(512) void final_kernel(const float* __restrict__ bn_w,
                                                    const float* __restrict__ bn_b,
                                                    const float* __restrict__ fw,
                                                    const float* __restrict__ fb,
                                                    float* __restrict__ out)
{
    __shared__ unsigned char sbin[Bb][Pp];   // 16 KB
    int p = threadIdx.x;                     // 0..511

    float x[Bb];
    float s = 0.0f;
    #pragma unroll
    for (int b = 0; b < Bb; b++) { x[b] = g_scores[b*Pp + p]; s += x[b]; }
    float mean = s * (1.0f / Bb);
    float v = 0.0f;
    #pragma unroll
    for (int b = 0; b < Bb; b++) { float d = x[b] - mean; v += d * d; }
    v *= (1.0f / Bb);                        // biased variance (training-mode BN)
    float inv = rsqrtf(v + 1e-5f);
    float w = bn_w[p], bb = bn_b[p];
    #pragma unroll
    for (int b = 0; b < Bb; b++) {
        float y = (x[b] - mean) * inv * w + bb;
        sbin[b][p] = (y > 0.0f) ? 1 : 0;     // sign(relu(y))
    }
    __syncthreads();

    // 64 outputs (b,c); 16 warps x 4 outputs each, lane-parallel over p
    int warp = p >> 5, lane = p & 31;
    #pragma unroll
    for (int q = 0; q < 4; q++) {
        int o = warp * 4 + q;
        int b = o >> 1, c = o & 1;
        float acc = 0.0f;
        for (int pp = lane; pp < Pp; pp += 32)
            if (sbin[b][pp]) acc += fw[c*Pp + pp];
        #pragma unroll
        for (int off = 16; off > 0; off >>= 1)
            acc += __shfl_xor_sync(0xffffffffu, acc, off);
        if (lane == 0) out[b*NCc + c] = acc + fb[c];
    }
}

// ---------------- launch ----------------
extern "C" void kernel_launch(void* const* d_in, const int* in_sizes, int n_in,
                              void* d_out, int out_size)
{
    const int*   tokens    = (const int*)  d_in[0];
    const int*   doc_lens  = (const int*)  d_in[1];
    const float* emb_table = (const float*)d_in[2];
    const float* diags     = (const float*)d_in[3];
    const float* bias      = (const float*)d_in[4];
    const float* epsilons  = (const float*)d_in[5];
    const float* bn_weight = (const float*)d_in[6];
    const float* bn_bias   = (const float*)d_in[7];
    const float* final_w   = (const float*)d_in[8];
    const float* final_b   = (const float*)d_in[9];
    float* out = (float*)d_out;

    gather_kernel<<<Mm, 128>>>(tokens, emb_table);
    padB_kernel<<<Kk, 128>>>(diags);

    dim3 grid(Kk / 128, Mm / 128);   // (56, 32)
    gemm_kernel<<<grid, 256>>>(bias);

    scan_kernel<<<(Bb*Pp + 127) / 128, 128>>>(doc_lens, epsilons);

    final_kernel<<<1, 512>>>(bn_weight, bn_bias, final_w, final_b, out);
}

// round 3
// speedup vs baseline: 1.5826x; 1.5826x over previous
#include <cuda_runtime.h>
#include <cuda_bf16.h>
#include <cstdint>

// ---------------- problem constants ----------------
#define Bb    32
#define Tt    128
#define Pp    512
#define MAXL  7
#define Dd    300
#define KSEG  304            // per-segment K (>=300, mult of 16)
#define KP    (4*KSEG)       // 1216 = 38*32
#define Nn    7168           // P*ND*MAXL
#define Mm    4096           // B*T
#define NCc   2
#define NEGV  (-1e30f)

// gemm tiling
#define BK    32
#define NKT   (KP/BK)        // 38
#define NSTG  4
#define ROWB  80             // smem row stride bytes (64 data + 16 pad -> conflict-free ldmatrix)
#define STAGE_A   (128*ROWB)        // 10240
#define STAGE_SZ  (2*STAGE_A)       // 20480 (A then B)
#define SMEM_GEMM (NSTG*STAGE_SZ)   // 81920

// ---------------- scratch ----------------
__device__ __nv_bfloat16 g_Aq[(size_t)Mm * KP];   // [h,h,m,m]
__device__ __nv_bfloat16 g_Bq[(size_t)Nn * KP];   // [h,m,h,m]
__device__ float g_ts[(size_t)Mm * Nn];           // 117 MB
__device__ float g_scores[Bb * Pp];

// ---------------- PTX helpers ----------------
__device__ __forceinline__ void cpasync16(uint32_t s, const void* g){
    asm volatile("cp.async.cg.shared.global [%0], [%1], 16;" :: "r"(s), "l"(g));
}
__device__ __forceinline__ void cp_commit(){
    asm volatile("cp.async.commit_group;" ::: "memory");
}
template<int N> __device__ __forceinline__ void cp_wait(){
    asm volatile("cp.async.wait_group %0;" :: "n"(N) : "memory");
}
__device__ __forceinline__ void ldsm4(uint32_t a, uint32_t& r0, uint32_t& r1, uint32_t& r2, uint32_t& r3){
    asm volatile("ldmatrix.sync.aligned.m8n8.x4.shared.b16 {%0,%1,%2,%3}, [%4];"
                 : "=r"(r0), "=r"(r1), "=r"(r2), "=r"(r3) : "r"(a));
}
__device__ __forceinline__ void mma16816(float* c, uint32_t a0, uint32_t a1, uint32_t a2, uint32_t a3,
                                         uint32_t b0, uint32_t b1){
    asm volatile("mma.sync.aligned.m16n8k16.row.col.f32.bf16.bf16.f32 "
                 "{%0,%1,%2,%3}, {%4,%5,%6,%7}, {%8,%9}, {%0,%1,%2,%3};"
                 : "+f"(c[0]), "+f"(c[1]), "+f"(c[2]), "+f"(c[3])
                 : "r"(a0), "r"(a1), "r"(a2), "r"(a3), "r"(b0), "r"(b1));
}

// ---------------- 1/2. split-precision conversion ----------------
__global__ void convA_kernel(const int* __restrict__ tokens, const float* __restrict__ emb){
    int mrow = blockIdx.x;
    int tok = tokens[mrow];
    __nv_bfloat16* row = g_Aq + (size_t)mrow * KP;
    const float* src = emb + (size_t)tok * Dd;
    for (int k = threadIdx.x; k < KSEG; k += blockDim.x){
        float x = (k < Dd) ? src[k] : 0.0f;
        __nv_bfloat16 h = __float2bfloat16(x);
        __nv_bfloat16 m = __float2bfloat16(x - __bfloat162float(h));
        row[0*KSEG + k] = h;  row[1*KSEG + k] = h;
        row[2*KSEG + k] = m;  row[3*KSEG + k] = m;
    }
}
__global__ void convB_kernel(const float* __restrict__ diags){
    int n = blockIdx.x;
    __nv_bfloat16* row = g_Bq + (size_t)n * KP;
    const float* src = diags + (size_t)n * Dd;
    for (int k = threadIdx.x; k < KSEG; k += blockDim.x){
        float x = (k < Dd) ? src[k] : 0.0f;
        __nv_bfloat16 h = __float2bfloat16(x);
        __nv_bfloat16 m = __float2bfloat16(x - __bfloat162float(h));
        row[0*KSEG + k] = h;  row[1*KSEG + k] = m;
        row[2*KSEG + k] = h;  row[3*KSEG + k] = m;
    }
}

// ---------------- 3. bf16 mma.sync GEMM: ts[m][n] = sum_k A'[m][k]*B'[n][k] + bias[n] ----------------
// CTA 128x128, BK=32, 256 threads = 8 warps (2 M x 4 N), warp tile 64x32.
__global__ __launch_bounds__(256, 2) void gemm_kernel(const float* __restrict__ bias)
{
    extern __shared__ char smem[];
    const uint32_t sb = (uint32_t)__cvta_generic_to_shared(smem);
    const int tid = threadIdx.x;
    const int lane = tid & 31, wid = tid >> 5;
    const int wm = wid & 1, wn = wid >> 1;
    const int blockM = blockIdx.y * 128;
    const int blockN = blockIdx.x * 128;

    const __nv_bfloat16* gA = g_Aq + (size_t)blockM * KP;
    const __nv_bfloat16* gB = g_Bq + (size_t)blockN * KP;

    // cp.async assignment: each thread loads one 32B run of one row (A and B)
    const int ldRow = tid >> 1;            // 0..127
    const int ldCh  = (tid & 1) * 2;       // chunk base 0 or 2 (16B chunks)
    const uint32_t sA_off = ldRow * ROWB + ldCh * 16;
    const size_t   gOff   = (size_t)ldRow * KP + ldCh * 8;   // elements

    // ldmatrix source addresses (per-lane)
    // A: tile i, kstep s: row = wm*64 + i*16 + (lane&15), chunk = (lane>>4)
    const uint32_t aBase = sb + (wm*64 + (lane & 15)) * ROWB + (lane >> 4) * 16;
    // B: pair j2, kstep s: q=lane>>3: row = wn*32 + (2*j2+(q>>1))*8 + (lane&7), chunk = q&1
    const uint32_t bBase = sb + STAGE_A + (wn*32 + ((lane >> 4) << 3) + (lane & 7)) * ROWB
                              + (((lane >> 3) & 1) * 16);

    float acc[4][4][4];
    #pragma unroll
    for (int i = 0; i < 4; i++)
        #pragma unroll
        for (int j = 0; j < 4; j++)
            #pragma unroll
            for (int r = 0; r < 4; r++) acc[i][j][r] = 0.0f;

    // prologue: load stages 0..NSTG-2
    #pragma unroll
    for (int s = 0; s < NSTG-1; s++){
        uint32_t st = sb + s*STAGE_SZ + sA_off;
        const __nv_bfloat16* pa = gA + gOff + s*BK;
        const __nv_bfloat16* pb = gB + gOff + s*BK;
        cpasync16(st,            pa);
        cpasync16(st + 16,       pa + 8);
        cpasync16(st + STAGE_A,      pb);
        cpasync16(st + STAGE_A + 16, pb + 8);
        cp_commit();
    }

    for (int kt = 0; kt < NKT; kt++){
        cp_wait<NSTG-2>();
        __syncthreads();

        // issue loads for stage kt+NSTG-1 (overwrites stage computed at kt-1)
        int nkt = kt + NSTG - 1;
        if (nkt < NKT){
            uint32_t st = sb + (nkt % NSTG)*STAGE_SZ + sA_off;
            const __nv_bfloat16* pa = gA + gOff + nkt*BK;
            const __nv_bfloat16* pb = gB + gOff + nkt*BK;
            cpasync16(st,            pa);
            cpasync16(st + 16,       pa + 8);
            cpasync16(st + STAGE_A,      pb);
            cpasync16(st + STAGE_A + 16, pb + 8);
        }
        cp_commit();

        // compute on stage kt%NSTG
        const uint32_t stage = (kt % NSTG) * STAGE_SZ;
        #pragma unroll
        for (int s = 0; s < 2; s++){
            uint32_t a[4][4], b[4][2];
            #pragma unroll
            for (int i = 0; i < 4; i++)
                ldsm4(aBase + stage + i*16*ROWB + s*32, a[i][0], a[i][1], a[i][2], a[i][3]);
            #pragma unroll
            for (int j2 = 0; j2 < 2; j2++){
                uint32_t r0, r1, r2, r3;
                ldsm4(bBase + stage + j2*16*ROWB + s*32, r0, r1, r2, r3);
                b[2*j2][0] = r0;  b[2*j2][1] = r1;
                b[2*j2+1][0] = r2; b[2*j2+1][1] = r3;
            }
            #pragma unroll
            for (int i = 0; i < 4; i++)
                #pragma unroll
                for (int j = 0; j < 4; j++)
                    mma16816(acc[i][j], a[i][0], a[i][1], a[i][2], a[i][3], b[j][0], b[j][1]);
        }
    }

    // epilogue: add bias, store float2 pairs
    const int colBase = blockN + wn*32 + 2*(lane & 3);
    float2 bj[4];
    #pragma unroll
    for (int j = 0; j < 4; j++) bj[j] = *(const float2*)(bias + colBase + j*8);

    #pragma unroll
    for (int i = 0; i < 4; i++){
        int row0 = blockM + wm*64 + i*16 + (lane >> 2);
        #pragma unroll
        for (int j = 0; j < 4; j++){
            float2 v0 = make_float2(acc[i][j][0] + bj[j].x, acc[i][j][1] + bj[j].y);
            float2 v1 = make_float2(acc[i][j][2] + bj[j].x, acc[i][j][3] + bj[j].y);
            *(float2*)(g_ts + (size_t)row0 * Nn + colBase + j*8)       = v0;
            *(float2*)(g_ts + (size_t)(row0+8) * Nn + colBase + j*8)   = v1;
        }
    }
}

// ---------------- 4. max-sum scan, unroll-4 with batched float2 loads ----------------
__global__ __launch_bounds__(128) void scan_kernel(const int* __restrict__ doc_lens,
                                                   const float* __restrict__ epsilons)
{
    int idx = blockIdx.x * 128 + threadIdx.x;
    int b = idx >> 9;
    int p = idx & 511;

    float eps[6];
    #pragma unroll
    for (int i = 0; i < 6; i++) eps[i] = epsilons[p*6 + i];
    const bool end5 = (p < 256);
    const int dl = doc_lens[b];

    float hid[7];
    hid[0] = 0.0f;
    #pragma unroll
    for (int m = 1; m < 7; m++) hid[m] = NEGV;
    float sc = NEGV;

    const float2* base = (const float2*)(g_ts + (size_t)b * Tt * Nn + (size_t)p * 14);

    for (int t0 = 0; t0 < Tt; t0 += 4){
        float2 v[4][7];
        #pragma unroll
        for (int u = 0; u < 4; u++){
            const float2* q = base + (size_t)(t0 + u) * (Nn/2);
            #pragma unroll
            for (int j = 0; j < 7; j++) v[u][j] = q[j];
        }
        #pragma unroll
        for (int u = 0; u < 4; u++){
            float f[14];
            #pragma unroll
            for (int j = 0; j < 7; j++){ f[2*j] = v[u][j].x; f[2*j+1] = v[u][j].y; }
            float ae[7];
            ae[0] = hid[0];
            #pragma unroll
            for (int m = 1; m < 7; m++) ae[m] = fmaxf(hid[m], hid[m-1] + eps[m-1]);
            float nh[7];
            nh[0] = fmaxf(0.0f, ae[0] + f[0]);
            #pragma unroll
            for (int m = 1; m < 7; m++)
                nh[m] = fmaxf(ae[m-1] + f[7 + m - 1], ae[m] + f[m]);
            #pragma unroll
            for (int m = 0; m < 7; m++) hid[m] = nh[m];
            float endv = end5 ? hid[5] : hid[6];
            if (t0 + u < dl) sc = fmaxf(sc, endv);
        }
    }
    g_scores[idx] = sc;
}

// ---------------- 5. batchnorm + binarize + final linear ----------------
__global__ __launch_bounds__(512) void final_kernel(const float* __restrict__ bn_w,
                                                    const float* __restrict__ bn_b,
                                                    const float* __restrict__ fw,
                                                    const float* __restrict__ fb,
                                                    float* __restrict__ out)
{
    __shared__ unsigned char sbin[Bb][Pp];
    int p = threadIdx.x;

    float x[Bb];
    float s = 0.0f;
    #pragma unroll
    for (int b = 0; b < Bb; b++){ x[b] = g_scores[b*Pp + p]; s += x[b]; }
    float mean = s * (1.0f / Bb);
    float v = 0.0f;
    #pragma unroll
    for (int b = 0; b < Bb; b++){ float d = x[b] - mean; v += d * d; }
    v *= (1.0f / Bb);
    float inv = rsqrtf(v + 1e-5f);
    float w = bn_w[p], bb = bn_b[p];
    #pragma unroll
    for (int b = 0; b < Bb; b++){
        float y = (x[b] - mean) * inv * w + bb;
        sbin[b][p] = (y > 0.0f) ? 1 : 0;
    }
    __syncthreads();

    int warp = p >> 5, lane = p & 31;
    #pragma unroll
    for (int q = 0; q < 4; q++){
        int o = warp * 4 + q;
        int b = o >> 1, c = o & 1;
        float acc = 0.0f;
        for (int pp = lane; pp < Pp; pp += 32)
            if (sbin[b][pp]) acc += fw[c*Pp + pp];
        #pragma unroll
        for (int off = 16; off > 0; off >>= 1)
            acc += __shfl_xor_sync(0xffffffffu, acc, off);
        if (lane == 0) out[b*NCc + c] = acc + fb[c];
    }
}

// ---------------- host launch ----------------
extern "C" void kernel_launch(void* const* d_in, const int* in_sizes, int n_in,
                              void* d_out, int out_size)
{
    const int*   tokens    = (const int*)  d_in[0];
    const int*   doc_lens  = (const int*)  d_in[1];
    const float* emb_table = (const float*)d_in[2];
    const float* diags     = (const float*)d_in[3];
    const float* bias      = (const float*)d_in[4];
    const float* epsilons  = (const float*)d_in[5];
    const float* bn_weight = (const float*)d_in[6];
    const float* bn_bias   = (const float*)d_in[7];
    const float* final_w   = (const float*)d_in[8];
    const float* final_b   = (const float*)d_in[9];
    float* out = (float*)d_out;

    convA_kernel<<<Mm, 128>>>(tokens, emb_table);
    convB_kernel<<<Nn, 128>>>(diags);

    cudaFuncSetAttribute(gemm_kernel, cudaFuncAttributeMaxDynamicSharedMemorySize, SMEM_GEMM);
    dim3 grid(Nn / 128, Mm / 128);   // (56, 32)
    gemm_kernel<<<grid, 256, SMEM_GEMM>>>(bias);

    scan_kernel<<<(Bb*Pp) / 128, 128>>>(doc_lens, epsilons);
    final_kernel<<<1, 512>>>(bn_weight, bn_bias, final_w, final_b, out);
}